// round 1
// baseline (speedup 1.0000x reference)
#include <cuda_runtime.h>
#include <math.h>

// Problem constants (fixed shapes for this problem instance)
#define VN   500000     // nodes
#define DD   128        // input feature dim
#define NEE  1000000    // hyperedges
#define KK   8          // vertices per hyperedge
#define CC   16         // layer-3 width
#define HH   8          // hidden width (layers 1,2)

// ---------------- scratch (device globals; no runtime allocation) ----------
__device__ float g_proj[VN];
__device__ float g_dinv[VN];
__device__ int   g_cnt[VN];
__device__ int   g_start[VN];
__device__ int   g_cursor[VN];
__device__ int   g_Se[NEE];
__device__ int   g_Ie[NEE];
__device__ int2  g_adj[2 * NEE];        // (neighbor, weight-as-bits)
__device__ float g_MA[(size_t)VN * 16];
__device__ float g_MB[(size_t)VN * 16];
__device__ int          g_is64;
__device__ unsigned int g_total;

// ---------------- 0) dtype detection + per-replay reset --------------------
// E is declared int64 in the reference, but JAX default config downcasts to
// int32. If data is int64 (little-endian), every odd 32-bit word of the first
// 256 entries is 0 (values in [0, 500000)). If it is int32, those words are
// random nonzero indices. Probability of misdetection ~ (2e-6)^256 == 0.
__global__ void k_detect(const unsigned int* __restrict__ E) {
    if (threadIdx.x == 0) {
        unsigned int acc = 0;
        #pragma unroll 8
        for (int i = 0; i < 256; i++) acc |= E[2 * i + 1];
        g_is64 = (acc == 0u) ? 1 : 0;
        g_total = 0u;   // CSR offset counter: must reset every graph replay
    }
}

// ---------------- 1) fused proj = X@rv and MA = X@W1; cnt=0 ----------------
__global__ void k_proj(const float* __restrict__ X,
                       const float* __restrict__ rv,
                       const float* __restrict__ W1) {
    __shared__ float s_rv[DD];
    __shared__ float s_W[DD * HH];
    for (int i = threadIdx.x; i < DD; i += blockDim.x)      s_rv[i] = rv[i];
    for (int i = threadIdx.x; i < DD * HH; i += blockDim.x) s_W[i]  = W1[i];
    __syncthreads();

    int v = blockIdx.x * blockDim.x + threadIdx.x;
    if (v >= VN) return;

    const float4* xr = (const float4*)(X + (size_t)v * DD);
    float p = 0.f;
    float h[HH];
    #pragma unroll
    for (int j = 0; j < HH; j++) h[j] = 0.f;

    #pragma unroll 8
    for (int i = 0; i < DD / 4; i++) {
        float4 x = __ldg(xr + i);
        float xs[4] = {x.x, x.y, x.z, x.w};
        int c = 4 * i;
        #pragma unroll
        for (int q = 0; q < 4; q++) {
            float xv = xs[q];
            p += xv * s_rv[c + q];
            const float* wrow = &s_W[(c + q) * HH];
            #pragma unroll
            for (int j = 0; j < HH; j++) h[j] += xv * wrow[j];
        }
    }

    g_proj[v] = p;
    g_cnt[v]  = 0;
    float4* m = (float4*)(g_MA + (size_t)v * HH);
    m[0] = make_float4(h[0], h[1], h[2], h[3]);
    m[1] = make_float4(h[4], h[5], h[6], h[7]);
}

// ---------------- 2) per-edge argmax/argmin of proj; degree histogram ------
__global__ void k_edges(const void* __restrict__ Eraw) {
    int e = blockIdx.x * blockDim.x + threadIdx.x;
    if (e >= NEE) return;

    int idx[KK];
    if (g_is64) {
        const longlong2* p = (const longlong2*)Eraw + (size_t)e * 4;
        #pragma unroll
        for (int i = 0; i < 4; i++) {
            longlong2 t = __ldg(p + i);
            idx[2 * i]     = (int)t.x;
            idx[2 * i + 1] = (int)t.y;
        }
    } else {
        const int4* p = (const int4*)Eraw + (size_t)e * 2;
        int4 a = __ldg(p), b = __ldg(p + 1);
        idx[0] = a.x; idx[1] = a.y; idx[2] = a.z; idx[3] = a.w;
        idx[4] = b.x; idx[5] = b.y; idx[6] = b.z; idx[7] = b.w;
    }

    // strict comparisons == first-occurrence semantics of jnp.argmax/argmin
    float p0 = __ldg(&g_proj[idx[0]]);
    float mx = p0, mn = p0;
    int am = idx[0], an = idx[0];
    #pragma unroll
    for (int i = 1; i < KK; i++) {
        float pv = __ldg(&g_proj[idx[i]]);
        if (pv > mx) { mx = pv; am = idx[i]; }
        if (pv < mn) { mn = pv; an = idx[i]; }
    }
    g_Se[e] = am;
    g_Ie[e] = an;
    atomicAdd(&g_cnt[am], 1);
    atomicAdd(&g_cnt[an], 1);
}

// ---------------- 3) dinv + CSR offsets (block scan, 1 atomic/block) -------
__global__ void k_offsets() {
    __shared__ int s_wsum[8];
    __shared__ int s_base;
    int v    = blockIdx.x * blockDim.x + threadIdx.x;
    int lane = threadIdx.x & 31;
    int wid  = threadIdx.x >> 5;

    int c = (v < VN) ? g_cnt[v] : 0;

    // warp inclusive scan
    int x = c;
    #pragma unroll
    for (int o = 1; o < 32; o <<= 1) {
        int y = __shfl_up_sync(0xffffffffu, x, o);
        if (lane >= o) x += y;
    }
    if (lane == 31) s_wsum[wid] = x;
    __syncthreads();

    if (threadIdx.x == 0) {
        int running = 0;
        #pragma unroll
        for (int i = 0; i < 8; i++) {
            int t = s_wsum[i];
            s_wsum[i] = running;
            running += t;
        }
        s_base = (int)atomicAdd(&g_total, (unsigned int)running);
    }
    __syncthreads();

    if (v < VN) {
        int start = s_base + s_wsum[wid] + (x - c);   // exclusive prefix
        g_start[v]  = start;
        g_cursor[v] = start;
        g_dinv[v]   = rsqrtf(1.0f + 0.125f * (float)c);
    }
}

// ---------------- 4) fill adjacency entries (weight precomputed) -----------
__global__ void k_fill() {
    int e = blockIdx.x * blockDim.x + threadIdx.x;
    if (e >= NEE) return;
    int s = g_Se[e], i = g_Ie[e];
    float w = 0.125f * g_dinv[s] * g_dinv[i];
    int wb = __float_as_int(w);
    int ps = atomicAdd(&g_cursor[s], 1);
    g_adj[ps] = make_int2(i, wb);
    int pi = atomicAdd(&g_cursor[i], 1);
    g_adj[pi] = make_int2(s, wb);
}

// ---------------- 5) fused layer: spmm -> +b -> relu -> @Wnext -------------
// AB = 0: read g_MA, write g_MB.  AB = 1: read g_MB, write g_MA.
template <int FIN, int FOUT, int AB>
__global__ void k_layer(const float* __restrict__ bias,
                        const float* __restrict__ W) {
    __shared__ float sW[FIN * FOUT];
    __shared__ float sb[FIN];
    for (int i = threadIdx.x; i < FIN * FOUT; i += blockDim.x) sW[i] = W[i];
    if (threadIdx.x < FIN) sb[threadIdx.x] = bias[threadIdx.x];
    __syncthreads();

    int v = blockIdx.x * blockDim.x + threadIdx.x;
    if (v >= VN) return;

    const float* Min = AB ? g_MB : g_MA;
    float*       Mout = AB ? g_MA : g_MB;

    float dv = g_dinv[v];
    float dd = dv * dv;

    float acc[FIN];
    const float4* mr = (const float4*)(Min + (size_t)v * FIN);
    #pragma unroll
    for (int q = 0; q < FIN / 4; q++) {
        float4 t = __ldg(mr + q);
        acc[4 * q + 0] = dd * t.x;
        acc[4 * q + 1] = dd * t.y;
        acc[4 * q + 2] = dd * t.z;
        acc[4 * q + 3] = dd * t.w;
    }

    int s = g_start[v];
    int e = s + g_cnt[v];
    for (int j = s; j < e; j++) {
        int2 ent = __ldg(&g_adj[j]);
        float w = __int_as_float(ent.y);
        const float4* nb = (const float4*)(Min + (size_t)ent.x * FIN);
        #pragma unroll
        for (int q = 0; q < FIN / 4; q++) {
            float4 t = __ldg(nb + q);
            acc[4 * q + 0] += w * t.x;
            acc[4 * q + 1] += w * t.y;
            acc[4 * q + 2] += w * t.z;
            acc[4 * q + 3] += w * t.w;
        }
    }

    float h[FIN];
    #pragma unroll
    for (int i = 0; i < FIN; i++) h[i] = fmaxf(acc[i] + sb[i], 0.f);

    float o[FOUT];
    #pragma unroll
    for (int j = 0; j < FOUT; j++) o[j] = 0.f;
    #pragma unroll
    for (int i = 0; i < FIN; i++) {
        #pragma unroll
        for (int j = 0; j < FOUT; j++) o[j] += h[i] * sW[i * FOUT + j];
    }

    float4* om = (float4*)(Mout + (size_t)v * FOUT);
    #pragma unroll
    for (int q = 0; q < FOUT / 4; q++)
        om[q] = make_float4(o[4 * q], o[4 * q + 1], o[4 * q + 2], o[4 * q + 3]);
}

// ---------------- 6) last layer: spmm -> relu -> fc -> sigmoid -------------
__global__ void k_last(float* __restrict__ out,
                       const float* __restrict__ b3,
                       const float* __restrict__ fcw,
                       const float* __restrict__ fcb) {
    __shared__ float sb[CC];
    __shared__ float sw[CC];
    __shared__ float sfcb;
    if (threadIdx.x < CC) {
        sb[threadIdx.x] = b3[threadIdx.x];
        sw[threadIdx.x] = fcw[threadIdx.x];
    }
    if (threadIdx.x == 0) sfcb = fcb[0];
    __syncthreads();

    int v = blockIdx.x * blockDim.x + threadIdx.x;
    if (v >= VN) return;

    const float* Min = g_MA;   // layer-2 output (F=16) lives in MA
    float dv = g_dinv[v];
    float dd = dv * dv;

    float acc[CC];
    const float4* mr = (const float4*)(Min + (size_t)v * CC);
    #pragma unroll
    for (int q = 0; q < CC / 4; q++) {
        float4 t = __ldg(mr + q);
        acc[4 * q + 0] = dd * t.x;
        acc[4 * q + 1] = dd * t.y;
        acc[4 * q + 2] = dd * t.z;
        acc[4 * q + 3] = dd * t.w;
    }

    int s = g_start[v];
    int e = s + g_cnt[v];
    for (int j = s; j < e; j++) {
        int2 ent = __ldg(&g_adj[j]);
        float w = __int_as_float(ent.y);
        const float4* nb = (const float4*)(Min + (size_t)ent.x * CC);
        #pragma unroll
        for (int q = 0; q < CC / 4; q++) {
            float4 t = __ldg(nb + q);
            acc[4 * q + 0] += w * t.x;
            acc[4 * q + 1] += w * t.y;
            acc[4 * q + 2] += w * t.z;
            acc[4 * q + 3] += w * t.w;
        }
    }

    float z = sfcb;
    #pragma unroll
    for (int i = 0; i < CC; i++)
        z += fmaxf(acc[i] + sb[i], 0.f) * sw[i];

    out[v] = 1.0f / (1.0f + expf(-z));
}

// ---------------- host: launch sequence (graph-capturable) -----------------
extern "C" void kernel_launch(void* const* d_in, const int* in_sizes, int n_in,
                              void* d_out, int out_size) {
    const float* X   = (const float*)d_in[0];
    const void*  E   = d_in[1];
    const float* rv  = (const float*)d_in[2];
    const float* W1  = (const float*)d_in[3];
    const float* b1  = (const float*)d_in[4];
    const float* W2  = (const float*)d_in[5];
    const float* b2  = (const float*)d_in[6];
    const float* W3  = (const float*)d_in[7];
    const float* b3  = (const float*)d_in[8];
    const float* fcw = (const float*)d_in[9];
    const float* fcb = (const float*)d_in[10];
    float* out = (float*)d_out;

    const int TB = 256;
    const int gV = (VN + TB - 1) / TB;
    const int gE = (NEE + TB - 1) / TB;

    k_detect<<<1, 32>>>((const unsigned int*)E);
    k_proj<<<gV, TB>>>(X, rv, W1);
    k_edges<<<gE, TB>>>(E);
    k_offsets<<<gV, TB>>>();
    k_fill<<<gE, TB>>>();
    k_layer<HH, HH, 0><<<gV, TB>>>(b1, W2);   // MA(8) -> MB(8)
    k_layer<HH, CC, 1><<<gV, TB>>>(b2, W3);   // MB(8) -> MA(16)
    k_last<<<gV, TB>>>(out, b3, fcw, fcb);
}

// round 2
// speedup vs baseline: 1.0420x; 1.0420x over previous
#include <cuda_runtime.h>
#include <math.h>

// Problem constants (fixed shapes for this problem instance)
#define VN   500000     // nodes
#define DD   128        // input feature dim
#define NEE  1000000    // hyperedges
#define KK   8          // vertices per hyperedge
#define CC   16         // layer-3 width
#define HH   8          // hidden width (layers 1,2)

// ---------------- scratch (device globals; no runtime allocation) ----------
__device__ float g_proj[VN];
__device__ float g_dinv[VN];
__device__ int   g_cnt[VN];
__device__ int   g_start[VN];
__device__ int   g_cursor[VN];
__device__ int   g_Se[NEE];
__device__ int   g_Ie[NEE];
__device__ int2  g_adj[2 * NEE];        // (neighbor, weight-as-bits)
__device__ float g_MA[(size_t)VN * 16];
__device__ float g_MB[(size_t)VN * 16];
__device__ int          g_is64;
__device__ unsigned int g_total;

// ---------------- 1) fused proj = X@rv, MA = X@W1, dtype detect, cnt=0 -----
// Shared-memory tiled: 256 nodes x 16 cols per tile, coalesced global loads,
// stride-20 smem rows (16B aligned; LDS.128 readout is bank-conflict-free:
// lanes 0-7 start banks {0,20,8,28,16,4,24,12} covering all 32 banks).
__global__ void __launch_bounds__(256) k_proj(
        const float* __restrict__ X,
        const float* __restrict__ rv,
        const float* __restrict__ W1,
        const unsigned int* __restrict__ Eraw) {
    __shared__ float sX[256 * 20];
    __shared__ float s_rv[DD];
    __shared__ float s_W[DD * HH];

    // dtype detection + per-replay counter reset (E int64 => odd words all 0)
    if (blockIdx.x == 0 && threadIdx.x == 0) {
        unsigned int acc = 0;
        #pragma unroll 8
        for (int i = 0; i < 256; i++) acc |= Eraw[2 * i + 1];
        g_is64 = (acc == 0u) ? 1 : 0;
        g_total = 0u;
    }

    for (int i = threadIdx.x; i < DD; i += 256)      s_rv[i] = rv[i];
    for (int i = threadIdx.x; i < DD * HH; i += 256) s_W[i]  = W1[i];

    int v0 = blockIdx.x * 256;
    int v  = v0 + threadIdx.x;

    float p = 0.f;
    float h[HH];
    #pragma unroll
    for (int j = 0; j < HH; j++) h[j] = 0.f;

    const float4* srv4 = (const float4*)s_rv;
    const float4* sW4  = (const float4*)s_W;

    #pragma unroll 1
    for (int t = 0; t < DD / 16; t++) {
        __syncthreads();
        // coalesced tile load: warp covers 2 rows x 16 contiguous floats
        #pragma unroll
        for (int rep = 0; rep < 16; rep++) {
            int i = rep * 256 + threadIdx.x;
            int r = i >> 4, c = i & 15;
            int vr = v0 + r;
            sX[r * 20 + c] = (vr < VN) ? X[(size_t)vr * DD + t * 16 + c] : 0.f;
        }
        __syncthreads();
        if (v < VN) {
            const float4* sx4 = (const float4*)(sX + threadIdx.x * 20);
            #pragma unroll
            for (int g = 0; g < 4; g++) {
                float4 x  = sx4[g];
                float4 r4 = srv4[t * 4 + g];
                p += x.x * r4.x + x.y * r4.y + x.z * r4.z + x.w * r4.w;
                int colbase = t * 16 + g * 4;
                #pragma unroll
                for (int q = 0; q < 4; q++) {
                    float xv = (&x.x)[q];
                    float4 wa = sW4[(colbase + q) * 2];
                    float4 wb = sW4[(colbase + q) * 2 + 1];
                    h[0] += xv * wa.x; h[1] += xv * wa.y;
                    h[2] += xv * wa.z; h[3] += xv * wa.w;
                    h[4] += xv * wb.x; h[5] += xv * wb.y;
                    h[6] += xv * wb.z; h[7] += xv * wb.w;
                }
            }
        }
    }

    if (v < VN) {
        g_proj[v] = p;
        g_cnt[v]  = 0;
        float4* m = (float4*)(g_MA + (size_t)v * HH);
        m[0] = make_float4(h[0], h[1], h[2], h[3]);
        m[1] = make_float4(h[4], h[5], h[6], h[7]);
    }
}

// ---------------- 2) per-edge argmax/argmin of proj; degree histogram ------
// E staged through shared via coalesced int4 loads; stride-9 index table
// gives conflict-free per-thread readout.
__global__ void __launch_bounds__(256) k_edges(const int4* __restrict__ E4) {
    __shared__ int sIdx[256 * 9];
    int e0 = blockIdx.x * 256;
    bool is64 = (g_is64 != 0);

    if (is64) {
        const int4* base = E4 + (size_t)e0 * 4;
        int lim = NEE * 4 - e0 * 4;
        for (int i = threadIdx.x; i < 1024; i += 256) {
            if (i < lim) {
                int4 x = __ldg(base + i);
                int e = i >> 2, pr = i & 3;
                sIdx[e * 9 + 2 * pr]     = x.x;   // low words of int64 pair
                sIdx[e * 9 + 2 * pr + 1] = x.z;
            }
        }
    } else {
        const int4* base = E4 + (size_t)e0 * 2;
        int lim = NEE * 2 - e0 * 2;
        for (int i = threadIdx.x; i < 512; i += 256) {
            if (i < lim) {
                int4 x = __ldg(base + i);
                int e = i >> 1, pr = i & 1;
                sIdx[e * 9 + 4 * pr]     = x.x;
                sIdx[e * 9 + 4 * pr + 1] = x.y;
                sIdx[e * 9 + 4 * pr + 2] = x.z;
                sIdx[e * 9 + 4 * pr + 3] = x.w;
            }
        }
    }
    __syncthreads();

    int e = e0 + threadIdx.x;
    if (e >= NEE) return;

    int idx[KK];
    #pragma unroll
    for (int k = 0; k < KK; k++) idx[k] = sIdx[threadIdx.x * 9 + k];

    // strict comparisons == first-occurrence semantics of jnp.argmax/argmin
    float p0 = __ldg(&g_proj[idx[0]]);
    float mx = p0, mn = p0;
    int am = idx[0], an = idx[0];
    #pragma unroll
    for (int i = 1; i < KK; i++) {
        float pv = __ldg(&g_proj[idx[i]]);
        if (pv > mx) { mx = pv; am = idx[i]; }
        if (pv < mn) { mn = pv; an = idx[i]; }
    }
    g_Se[e] = am;
    g_Ie[e] = an;
    atomicAdd(&g_cnt[am], 1);
    atomicAdd(&g_cnt[an], 1);
}

// ---------------- 3) dinv + CSR offsets (block scan, 1 atomic/block) -------
__global__ void __launch_bounds__(256) k_offsets() {
    __shared__ int s_wsum[8];
    __shared__ int s_base;
    int v    = blockIdx.x * blockDim.x + threadIdx.x;
    int lane = threadIdx.x & 31;
    int wid  = threadIdx.x >> 5;

    int c = (v < VN) ? g_cnt[v] : 0;

    int x = c;
    #pragma unroll
    for (int o = 1; o < 32; o <<= 1) {
        int y = __shfl_up_sync(0xffffffffu, x, o);
        if (lane >= o) x += y;
    }
    if (lane == 31) s_wsum[wid] = x;
    __syncthreads();

    if (threadIdx.x == 0) {
        int running = 0;
        #pragma unroll
        for (int i = 0; i < 8; i++) {
            int t = s_wsum[i];
            s_wsum[i] = running;
            running += t;
        }
        s_base = (int)atomicAdd(&g_total, (unsigned int)running);
    }
    __syncthreads();

    if (v < VN) {
        int start = s_base + s_wsum[wid] + (x - c);
        g_start[v]  = start;
        g_cursor[v] = start;
        g_dinv[v]   = rsqrtf(1.0f + 0.125f * (float)c);
    }
}

// ---------------- 4) fill adjacency entries (weight precomputed) -----------
__global__ void __launch_bounds__(256) k_fill() {
    int e = blockIdx.x * blockDim.x + threadIdx.x;
    if (e >= NEE) return;
    int s = g_Se[e], i = g_Ie[e];
    float w = 0.125f * g_dinv[s] * g_dinv[i];
    int wb = __float_as_int(w);
    int ps = atomicAdd(&g_cursor[s], 1);
    g_adj[ps] = make_int2(i, wb);
    int pi = atomicAdd(&g_cursor[i], 1);
    g_adj[pi] = make_int2(s, wb);
}

// ---------------- 5) fused layer: spmm -> +b -> relu -> @Wnext -------------
// Unroll-by-2 neighbor loop: two independent adj loads + two independent
// gather chains per iteration (double the MLP of the latency-bound loop).
template <int FIN, int FOUT, int AB>
__global__ void __launch_bounds__(256) k_layer(const float* __restrict__ bias,
                                               const float* __restrict__ W) {
    __shared__ float sW[FIN * FOUT];
    __shared__ float sb[FIN];
    for (int i = threadIdx.x; i < FIN * FOUT; i += blockDim.x) sW[i] = W[i];
    if (threadIdx.x < FIN) sb[threadIdx.x] = bias[threadIdx.x];
    __syncthreads();

    int v = blockIdx.x * blockDim.x + threadIdx.x;
    if (v >= VN) return;

    const float* Min  = AB ? g_MB : g_MA;
    float*       Mout = AB ? g_MA : g_MB;

    float dv = g_dinv[v];
    float dd = dv * dv;

    float acc[FIN];
    const float4* mr = (const float4*)(Min + (size_t)v * FIN);
    #pragma unroll
    for (int q = 0; q < FIN / 4; q++) {
        float4 t = __ldg(mr + q);
        acc[4 * q + 0] = dd * t.x;
        acc[4 * q + 1] = dd * t.y;
        acc[4 * q + 2] = dd * t.z;
        acc[4 * q + 3] = dd * t.w;
    }

    int s   = g_start[v];
    int end = s + g_cnt[v];
    int j   = s;
    #pragma unroll 1
    for (; j + 2 <= end; j += 2) {
        int2 e0 = __ldg(&g_adj[j]);
        int2 e1 = __ldg(&g_adj[j + 1]);
        float w0 = __int_as_float(e0.y);
        float w1 = __int_as_float(e1.y);
        const float4* n0 = (const float4*)(Min + (size_t)e0.x * FIN);
        const float4* n1 = (const float4*)(Min + (size_t)e1.x * FIN);
        #pragma unroll
        for (int q = 0; q < FIN / 4; q++) {
            float4 t0 = __ldg(n0 + q);
            float4 t1 = __ldg(n1 + q);
            acc[4 * q + 0] += w0 * t0.x + w1 * t1.x;
            acc[4 * q + 1] += w0 * t0.y + w1 * t1.y;
            acc[4 * q + 2] += w0 * t0.z + w1 * t1.z;
            acc[4 * q + 3] += w0 * t0.w + w1 * t1.w;
        }
    }
    if (j < end) {
        int2 e0 = __ldg(&g_adj[j]);
        float w0 = __int_as_float(e0.y);
        const float4* n0 = (const float4*)(Min + (size_t)e0.x * FIN);
        #pragma unroll
        for (int q = 0; q < FIN / 4; q++) {
            float4 t0 = __ldg(n0 + q);
            acc[4 * q + 0] += w0 * t0.x;
            acc[4 * q + 1] += w0 * t0.y;
            acc[4 * q + 2] += w0 * t0.z;
            acc[4 * q + 3] += w0 * t0.w;
        }
    }

    float hh[FIN];
    #pragma unroll
    for (int i = 0; i < FIN; i++) hh[i] = fmaxf(acc[i] + sb[i], 0.f);

    float o[FOUT];
    #pragma unroll
    for (int jj = 0; jj < FOUT; jj++) o[jj] = 0.f;
    #pragma unroll
    for (int i = 0; i < FIN; i++) {
        #pragma unroll
        for (int jj = 0; jj < FOUT; jj++) o[jj] += hh[i] * sW[i * FOUT + jj];
    }

    float4* om = (float4*)(Mout + (size_t)v * FOUT);
    #pragma unroll
    for (int q = 0; q < FOUT / 4; q++)
        om[q] = make_float4(o[4 * q], o[4 * q + 1], o[4 * q + 2], o[4 * q + 3]);
}

// ---------------- 6) last layer: spmm -> relu -> fc -> sigmoid -------------
__global__ void __launch_bounds__(256) k_last(float* __restrict__ out,
                                              const float* __restrict__ b3,
                                              const float* __restrict__ fcw,
                                              const float* __restrict__ fcb) {
    __shared__ float sb[CC];
    __shared__ float sw[CC];
    __shared__ float sfcb;
    if (threadIdx.x < CC) {
        sb[threadIdx.x] = b3[threadIdx.x];
        sw[threadIdx.x] = fcw[threadIdx.x];
    }
    if (threadIdx.x == 0) sfcb = fcb[0];
    __syncthreads();

    int v = blockIdx.x * blockDim.x + threadIdx.x;
    if (v >= VN) return;

    const float* Min = g_MA;   // layer-2 output (F=16) lives in MA
    float dv = g_dinv[v];
    float dd = dv * dv;

    float acc[CC];
    const float4* mr = (const float4*)(Min + (size_t)v * CC);
    #pragma unroll
    for (int q = 0; q < CC / 4; q++) {
        float4 t = __ldg(mr + q);
        acc[4 * q + 0] = dd * t.x;
        acc[4 * q + 1] = dd * t.y;
        acc[4 * q + 2] = dd * t.z;
        acc[4 * q + 3] = dd * t.w;
    }

    int s   = g_start[v];
    int end = s + g_cnt[v];
    int j   = s;
    #pragma unroll 1
    for (; j + 2 <= end; j += 2) {
        int2 e0 = __ldg(&g_adj[j]);
        int2 e1 = __ldg(&g_adj[j + 1]);
        float w0 = __int_as_float(e0.y);
        float w1 = __int_as_float(e1.y);
        const float4* n0 = (const float4*)(Min + (size_t)e0.x * CC);
        const float4* n1 = (const float4*)(Min + (size_t)e1.x * CC);
        #pragma unroll
        for (int q = 0; q < CC / 4; q++) {
            float4 t0 = __ldg(n0 + q);
            float4 t1 = __ldg(n1 + q);
            acc[4 * q + 0] += w0 * t0.x + w1 * t1.x;
            acc[4 * q + 1] += w0 * t0.y + w1 * t1.y;
            acc[4 * q + 2] += w0 * t0.z + w1 * t1.z;
            acc[4 * q + 3] += w0 * t0.w + w1 * t1.w;
        }
    }
    if (j < end) {
        int2 e0 = __ldg(&g_adj[j]);
        float w0 = __int_as_float(e0.y);
        const float4* n0 = (const float4*)(Min + (size_t)e0.x * CC);
        #pragma unroll
        for (int q = 0; q < CC / 4; q++) {
            float4 t0 = __ldg(n0 + q);
            acc[4 * q + 0] += w0 * t0.x;
            acc[4 * q + 1] += w0 * t0.y;
            acc[4 * q + 2] += w0 * t0.z;
            acc[4 * q + 3] += w0 * t0.w;
        }
    }

    float z = sfcb;
    #pragma unroll
    for (int i = 0; i < CC; i++)
        z += fmaxf(acc[i] + sb[i], 0.f) * sw[i];

    out[v] = 1.0f / (1.0f + expf(-z));
}

// ---------------- host: launch sequence (graph-capturable) -----------------
extern "C" void kernel_launch(void* const* d_in, const int* in_sizes, int n_in,
                              void* d_out, int out_size) {
    const float* X   = (const float*)d_in[0];
    const void*  E   = d_in[1];
    const float* rv  = (const float*)d_in[2];
    const float* W1  = (const float*)d_in[3];
    const float* b1  = (const float*)d_in[4];
    const float* W2  = (const float*)d_in[5];
    const float* b2  = (const float*)d_in[6];
    const float* W3  = (const float*)d_in[7];
    const float* b3  = (const float*)d_in[8];
    const float* fcw = (const float*)d_in[9];
    const float* fcb = (const float*)d_in[10];
    float* out = (float*)d_out;

    const int TB = 256;
    const int gV = (VN + TB - 1) / TB;
    const int gE = (NEE + TB - 1) / TB;

    k_proj<<<gV, TB>>>(X, rv, W1, (const unsigned int*)E);
    k_edges<<<gE, TB>>>((const int4*)E);
    k_offsets<<<gV, TB>>>();
    k_fill<<<gE, TB>>>();
    k_layer<HH, HH, 0><<<gV, TB>>>(b1, W2);   // MA(8) -> MB(8)
    k_layer<HH, CC, 1><<<gV, TB>>>(b2, W3);   // MB(8) -> MA(16)
    k_last<<<gV, TB>>>(out, b3, fcw, fcb);
}